// round 13
// baseline (speedup 1.0000x reference)
#include <cuda_runtime.h>
#include <cuda_bf16.h>
#include <cstdint>

#define DV      256
#define KEMB    1024
#define MTILE   128
#define NTILE   128
#define NCHUNK  8

/* dynamic smem layout (bytes) */
#define OFF_A       0        /* 128 x 256B X tile: chunks 0-7 fp8 / 8-15 int8 */
#define OFF_B       32768    /* 128 x 256B E chunk, same format split        */
#define OFF_SC      65536    /* 1024 x float4 {selo, sehi, bias, -} = 16KB   */
#define OFF_SX      81920    /* 128 x float2 {sxlo, sxhi} = 1KB              */
#define OFF_CAND    82944    /* 128 rows x 32 packed cands = 16KB            */
#define OFF_IDX     99328    /* 128 ints winning index per row               */
#define OFF_RED     99840    /* 8 doubles loss partials                      */
#define SMEM_TOTAL  99904

#define FP8_MAX  240.0f

__device__ __align__(16) uint32_t g_emb_q[KEMB * (DV / 4)];
__device__ __align__(16) float4 g_sc4[KEMB];  /* {selo, sehi, 16-0.5||e||^2, 0} */
__device__ float  g_bsq[KEMB];                /* ||e||^2 ref-order fp32 */
__device__ double g_loss_acc;

static __device__ __forceinline__ uint32_t smem_u32(const void* p) {
    uint32_t a;
    asm("{ .reg .u64 t; cvta.to.shared.u64 t, %1; cvt.u32.u64 %0, t; }" : "=r"(a) : "l"(p));
    return a;
}

/* XOR swizzle on 16B chunks within a 256B row */
static __device__ __forceinline__ uint32_t swz(int row, int chunk) {
    return (uint32_t)(row * 256) + (uint32_t)((chunk ^ (row & 7)) << 4);
}

static __device__ __forceinline__ void ldsm4(uint32_t* r, uint32_t addr) {
    asm volatile("ldmatrix.sync.aligned.m8n8.x4.shared.b16 {%0,%1,%2,%3}, [%4];"
                 : "=r"(r[0]), "=r"(r[1]), "=r"(r[2]), "=r"(r[3]) : "r"(addr));
}

/* e4m3 MMA: D[16,8] += A[16,32]*B[32,8], f32 accum */
static __device__ __forceinline__ void mmaf8(float* c, const uint32_t* a,
                                             uint32_t b0, uint32_t b1) {
    asm volatile(
        "mma.sync.aligned.m16n8k32.row.col.f32.e4m3.e4m3.f32 "
        "{%0,%1,%2,%3}, {%4,%5,%6,%7}, {%8,%9}, {%0,%1,%2,%3};"
        : "+f"(c[0]), "+f"(c[1]), "+f"(c[2]), "+f"(c[3])
        : "r"(a[0]), "r"(a[1]), "r"(a[2]), "r"(a[3]), "r"(b0), "r"(b1));
}

/* s8 IMMA: D[16,8] += A[16,32]*B[32,8], s32 accum */
static __device__ __forceinline__ void imma16832(int* c, const uint32_t* a,
                                                 uint32_t b0, uint32_t b1) {
    asm volatile(
        "mma.sync.aligned.m16n8k32.row.col.s32.s8.s8.s32 "
        "{%0,%1,%2,%3}, {%4,%5,%6,%7}, {%8,%9}, {%0,%1,%2,%3};"
        : "+r"(c[0]), "+r"(c[1]), "+r"(c[2]), "+r"(c[3])
        : "r"(a[0]), "r"(a[1]), "r"(a[2]), "r"(a[3]), "r"(b0), "r"(b1));
}

/* sorted top-4 insert on packed {score|idx} uints */
static __device__ __forceinline__ void ins4(uint32_t* L, uint32_t pb) {
    if (pb > L[3]) {
        if (pb > L[1]) {
            if (pb > L[0]) { L[3] = L[2]; L[2] = L[1]; L[1] = L[0]; L[0] = pb; }
            else           { L[3] = L[2]; L[2] = L[1]; L[1] = pb; }
        } else {
            if (pb > L[2]) { L[3] = L[2]; L[2] = pb; }
            else           { L[3] = pb; }
        }
    }
}

static __device__ __forceinline__ uint32_t pack4f8(float4 v, float inv) {
    uint16_t lo, hi;
    asm("cvt.rn.satfinite.e4m3x2.f32 %0, %1, %2;" : "=h"(lo) : "f"(v.y * inv), "f"(v.x * inv));
    asm("cvt.rn.satfinite.e4m3x2.f32 %0, %1, %2;" : "=h"(hi) : "f"(v.w * inv), "f"(v.z * inv));
    return (uint32_t)lo | ((uint32_t)hi << 16);
}
static __device__ __forceinline__ uint32_t pack4i8(float4 v, float inv) {
    int a = __float2int_rn(v.x * inv) & 255;
    int b = __float2int_rn(v.y * inv) & 255;
    int c = __float2int_rn(v.z * inv) & 255;
    int d = __float2int_rn(v.w * inv) & 255;
    return (uint32_t)a | ((uint32_t)b << 8) | ((uint32_t)c << 16) | ((uint32_t)d << 24);
}

/* ---------------- Kernel A: codebook prep ----------------
   dims 0-127 -> e4m3 (scale selo), dims 128-255 -> int8 (scale sehi);
   ||e||^2 in the reference's exact sequential unfused order. */
__global__ void vq_prep(const float* __restrict__ emb) {
    int b = blockIdx.x, t = threadIdx.x;           /* 1024 blocks x 256 threads */
    float v = emb[(size_t)b * DV + t];
    float av = fabsf(v);
#pragma unroll
    for (int o = 16; o; o >>= 1) av = fmaxf(av, __shfl_xor_sync(0xffffffffu, av, o));
    __shared__ float sw[8];
    __shared__ float smx[2];
    if ((t & 31) == 0) sw[t >> 5] = av;
    __syncthreads();
    if (t < 2) {
        float m = sw[t * 4];
#pragma unroll
        for (int i = 1; i < 4; i++) m = fmaxf(m, sw[t * 4 + i]);
        smx[t] = m;
    }
    __syncthreads();
    int half = t >> 7;
    float m = smx[half];
    uint32_t qb;
    if (half == 0) {
        uint16_t h;
        float sv = v * (FP8_MAX / m);
        asm("cvt.rn.satfinite.e4m3x2.f32 %0, %1, %2;" : "=h"(h) : "f"(0.f), "f"(sv));
        qb = (uint32_t)(h & 255u);
    } else {
        qb = (uint32_t)(__float2int_rn(v * (127.0f / m)) & 255);
    }
    uint32_t p1 = __shfl_down_sync(0xffffffffu, qb, 1);
    uint32_t p2 = __shfl_down_sync(0xffffffffu, qb, 2);
    uint32_t p3 = __shfl_down_sync(0xffffffffu, qb, 3);
    if ((t & 3) == 0)
        g_emb_q[b * 64 + (t >> 2)] = qb | (p1 << 8) | (p2 << 16) | (p3 << 24);
    if (t == 0) {
        const float4* er = (const float4*)(emb + (size_t)b * DV);
        float s = 0.f;
#pragma unroll 8
        for (int i = 0; i < DV / 4; i++) {
            float4 e = er[i];
            s = __fadd_rn(s, __fmul_rn(e.x, e.x));
            s = __fadd_rn(s, __fmul_rn(e.y, e.y));
            s = __fadd_rn(s, __fmul_rn(e.z, e.z));
            s = __fadd_rn(s, __fmul_rn(e.w, e.w));
        }
        g_bsq[b] = s;
        g_sc4[b] = make_float4(smx[0] * (1.0f / FP8_MAX), smx[1] * (1.0f / 127.0f),
                               16.0f - 0.5f * s, 0.f);
        if (b == 0) g_loss_acc = 0.0;
    }
}

/* ---------------- Kernel B: main ---------------- */
__global__ void __launch_bounds__(256, 2)
vq_main(const float* __restrict__ x, const float* __restrict__ emb, float* __restrict__ outq) {
    extern __shared__ char smem[];
    const uint32_t sb = smem_u32(smem);
    const int t = threadIdx.x;
    const int w = t >> 5;
    const int l = t & 31;
    const int m0 = blockIdx.x * MTILE;

    /* ---- stage per-code {selo, sehi, bias} table ---- */
    {
        const float4* src = (const float4*)g_sc4;
        float4* dst = (float4*)(smem + OFF_SC);
#pragma unroll
        for (int i = 0; i < 4; i++) dst[i * 256 + t] = src[i * 256 + t];
    }

    /* ---- X: per-half absmax, fp8 quant lo half / int8 quant hi half ---- */
    {
        int row = t >> 1, half = t & 1;
        const float4* xr = (const float4*)(x + (size_t)(m0 + row) * DV + half * 128);
        float mx = 0.f;
#pragma unroll 8
        for (int i = 0; i < 32; i++) {
            float4 v = xr[i];
            mx = fmaxf(mx, fmaxf(fmaxf(fabsf(v.x), fabsf(v.y)), fmaxf(fabsf(v.z), fabsf(v.w))));
        }
        if (half == 0) {
            ((float*)(smem + OFF_SX))[row * 2] = mx * (1.0f / FP8_MAX);
            float inv = FP8_MAX / mx;
#pragma unroll
            for (int c = 0; c < 8; c++) {
                uint4 st;
                st.x = pack4f8(xr[4 * c + 0], inv);
                st.y = pack4f8(xr[4 * c + 1], inv);
                st.z = pack4f8(xr[4 * c + 2], inv);
                st.w = pack4f8(xr[4 * c + 3], inv);
                *reinterpret_cast<uint4*>(smem + OFF_A + swz(row, c)) = st;
            }
        } else {
            ((float*)(smem + OFF_SX))[row * 2 + 1] = mx * (1.0f / 127.0f);
            float inv = 127.0f / mx;
#pragma unroll
            for (int c = 0; c < 8; c++) {
                uint4 st;
                st.x = pack4i8(xr[4 * c + 0], inv);
                st.y = pack4i8(xr[4 * c + 1], inv);
                st.z = pack4i8(xr[4 * c + 2], inv);
                st.w = pack4i8(xr[4 * c + 3], inv);
                *reinterpret_cast<uint4*>(smem + OFF_A + swz(row, 8 + c)) = st;
            }
        }
    }
    __syncthreads();

    /* warp tile: rows wr..wr+31, cols wc..wc+63 */
    const int wr = (w >> 1) * 32, wc = (w & 1) * 64;
    const uint32_t aoff = (uint32_t)(l >> 4);
    const uint32_t boff = (uint32_t)((l >> 3) & 1);
    uint32_t aAddr[2], aX[2], bAddr[4], bX[4];
#pragma unroll
    for (int i = 0; i < 2; i++) {
        int r = wr + i * 16 + (l & 7) + ((l >> 3) & 1) * 8;
        aAddr[i] = sb + OFF_A + (uint32_t)(r * 256);
        aX[i] = (uint32_t)(r & 7);
    }
#pragma unroll
    for (int nt = 0; nt < 4; nt++) {
        int r = wc + nt * 16 + (l & 7) + ((l >= 16) ? 8 : 0);
        bAddr[nt] = sb + OFF_B + (uint32_t)(r * 256);
        bX[nt] = (uint32_t)(r & 7);
    }
    const int erow = wr + (l >> 2);
    const int ecol = wc + (l & 3) * 2;

    float sxl[4], sxh[4];
#pragma unroll
    for (int ri = 0; ri < 4; ri++) {
        int r = erow + (ri >> 1) * 16 + (ri & 1) * 8;
        float2 sc = ((const float2*)(smem + OFF_SX))[r];
        sxl[ri] = sc.x; sxh[ri] = sc.y;
    }

    uint32_t L[4][4];
#pragma unroll
    for (int ri = 0; ri < 4; ri++)
#pragma unroll
        for (int p = 0; p < 4; p++) L[ri][p] = 0u;

    const float4* scp = (const float4*)(smem + OFF_SC);

    for (int c = 0; c < NCHUNK; c++) {
        if (c) __syncthreads();
        /* ---- load E chunk c (dual-format 256B rows) ---- */
        {
            int row = t >> 1, half = t & 1;
            const uint4* er = (const uint4*)(g_emb_q + (size_t)(c * NTILE + row) * 64) + half * 8;
#pragma unroll
            for (int k = 0; k < 8; k++)
                *reinterpret_cast<uint4*>(smem + OFF_B + swz(row, half * 8 + k)) = er[k];
        }
        __syncthreads();

        /* ---- two j-passes of 4 tiles; interleave fp8 + int8 k-steps ---- */
#pragma unroll
        for (int pass = 0; pass < 2; pass++) {
            float accf[2][4][4];
            int   acci[2][4][4];
#pragma unroll
            for (int i = 0; i < 2; i++)
#pragma unroll
                for (int jl = 0; jl < 4; jl++)
#pragma unroll
                    for (int q = 0; q < 4; q++) { accf[i][jl][q] = 0.f; acci[i][jl][q] = 0; }

#pragma unroll
            for (int s = 0; s < 4; s++) {
                uint32_t a8[2][4], b8[2][4];
#pragma unroll
                for (int i = 0; i < 2; i++)
                    ldsm4(a8[i], aAddr[i] + ((((uint32_t)(2 * s) + aoff) ^ aX[i]) << 4));
#pragma unroll
                for (int q = 0; q < 2; q++) {
                    int nt = pass * 2 + q;
                    ldsm4(b8[q], bAddr[nt] + ((((uint32_t)(2 * s) + boff) ^ bX[nt]) << 4));
                }
#pragma unroll
                for (int i = 0; i < 2; i++)
#pragma unroll
                    for (int jl = 0; jl < 4; jl++)
                        mmaf8(accf[i][jl], a8[i], b8[jl >> 1][(jl & 1) * 2], b8[jl >> 1][(jl & 1) * 2 + 1]);

                uint32_t ai[2][4], bi[2][4];
#pragma unroll
                for (int i = 0; i < 2; i++)
                    ldsm4(ai[i], aAddr[i] + ((((uint32_t)(8 + 2 * s) + aoff) ^ aX[i]) << 4));
#pragma unroll
                for (int q = 0; q < 2; q++) {
                    int nt = pass * 2 + q;
                    ldsm4(bi[q], bAddr[nt] + ((((uint32_t)(8 + 2 * s) + boff) ^ bX[nt]) << 4));
                }
#pragma unroll
                for (int i = 0; i < 2; i++)
#pragma unroll
                    for (int jl = 0; jl < 4; jl++)
                        imma16832(acci[i][jl], ai[i], bi[jl >> 1][(jl & 1) * 2], bi[jl >> 1][(jl & 1) * 2 + 1]);
            }

            /* ---- scan this pass: s = sxl*selo*dotf + sxh*sehi*doti + bias ---- */
#pragma unroll
            for (int jl = 0; jl < 4; jl++) {
                int colg = c * NTILE + ecol + (pass * 4 + jl) * 8;
                float4 p0 = scp[colg];
                float4 p1 = scp[colg + 1];
#pragma unroll
                for (int ri = 0; ri < 4; ri++) {
                    int i = ri >> 1, qb = (ri & 1) * 2;
                    float g0 = __int2float_rn(acci[i][jl][qb]);
                    float g1 = __int2float_rn(acci[i][jl][qb + 1]);
                    float s0 = __fmaf_rn(sxh[ri], p0.y * g0,
                               __fmaf_rn(sxl[ri], p0.x * accf[i][jl][qb], p0.z));
                    float s1 = __fmaf_rn(sxh[ri], p1.y * g1,
                               __fmaf_rn(sxl[ri], p1.x * accf[i][jl][qb + 1], p1.w + p1.z));
                    /* note: p1.w == 0, kept for symmetry */
                    ins4(L[ri], (__float_as_uint(s0) & 0xFFFFFC00u) | (uint32_t)colg);
                    ins4(L[ri], (__float_as_uint(s1) & 0xFFFFFC00u) | (uint32_t)(colg + 1));
                }
            }
        }
    }
    __syncthreads();

    /* ---- publish candidate lists: row r gets 32 packed entries ---- */
    {
        uint32_t* cand = (uint32_t*)(smem + OFF_CAND);
#pragma unroll
        for (int ri = 0; ri < 4; ri++) {
            int r = erow + (ri >> 1) * 16 + (ri & 1) * 8;
            *reinterpret_cast<uint4*>(cand + r * 32 + (w & 1) * 16 + (l & 3) * 4) =
                make_uint4(L[ri][0], L[ri][1], L[ri][2], L[ri][3]);
        }
    }
    __syncthreads();

    /* ---- refinement: replicate the reference's fp32 arithmetic ORDER
            (validated R8): A = seq unfused sum of x*x; M = seq FMA chain;
            d = fl(fl(A+B) - 2*M); argmin ties -> lowest index. ---- */
    double bestd64 = 0.0;
    if (t < 128) {
        const uint32_t* cl = (const uint32_t*)(smem + OFF_CAND) + t * 32;
        uint32_t cb[32];
#pragma unroll
        for (int k = 0; k < 8; k++)
            *reinterpret_cast<uint4*>(cb + k * 4) = reinterpret_cast<const uint4*>(cl)[k];
        uint32_t bestpb = 0;
#pragma unroll
        for (int k = 0; k < 32; k++) bestpb = max(bestpb, cb[k]);
        float thrv = __uint_as_float(bestpb & 0xFFFFFC00u) - 0.25f;

        const float4* xr = (const float4*)(x + (size_t)(m0 + t) * DV);
        float Af = 0.f;
#pragma unroll 8
        for (int i = 0; i < DV / 4; i++) {
            float4 v = xr[i];
            Af = __fadd_rn(Af, __fmul_rn(v.x, v.x));
            Af = __fadd_rn(Af, __fmul_rn(v.y, v.y));
            Af = __fadd_rn(Af, __fmul_rn(v.z, v.z));
            Af = __fadd_rn(Af, __fmul_rn(v.w, v.w));
        }

        float bestq = 3.4e38f; int besti = 0x7fffffff;
#pragma unroll 1
        for (int k = 0; k < 32; k++) {
            uint32_t pb = cb[k];
            if (__uint_as_float(pb & 0xFFFFFC00u) < thrv) continue;
            int idx = (int)(pb & 1023u);
            const float4* er = (const float4*)(emb + (size_t)idx * DV);
            float Mf = 0.f;
#pragma unroll 8
            for (int i = 0; i < DV / 4; i++) {
                float4 xv = xr[i]; float4 ev = er[i];
                Mf = __fmaf_rn(xv.x, ev.x, Mf);
                Mf = __fmaf_rn(xv.y, ev.y, Mf);
                Mf = __fmaf_rn(xv.z, ev.z, Mf);
                Mf = __fmaf_rn(xv.w, ev.w, Mf);
            }
            float Bf = g_bsq[idx];
            float dq = __fsub_rn(__fadd_rn(Af, Bf), __fmul_rn(2.0f, Mf));
            if (dq < bestq || (dq == bestq && idx < besti)) { bestq = dq; besti = idx; }
        }
        ((int*)(smem + OFF_IDX))[t] = besti;
        bestd64 = (double)bestq;
    }

    /* ---- loss reduction ---- */
    {
        double v = (t < 128) ? bestd64 : 0.0;
#pragma unroll
        for (int o = 16; o; o >>= 1)
            v += __longlong_as_double(__shfl_down_sync(0xffffffffu, __double_as_longlong(v), o));
        if (l == 0) ((double*)(smem + OFF_RED))[w] = v;
    }
    __syncthreads();
    if (t == 0) {
        double s = 0.0;
#pragma unroll
        for (int i = 0; i < 8; i++) s += ((double*)(smem + OFF_RED))[i];
        atomicAdd(&g_loss_acc, s);
    }

    /* ---- coalesced gather write: out[row] = emb[idx[row]] ---- */
    const int* sidx = (const int*)(smem + OFF_IDX);
    const float4* e4 = (const float4*)emb;
    float4* o4 = (float4*)outq;
#pragma unroll 4
    for (int i = t; i < MTILE * (DV / 4); i += 256) {
        int r = i >> 6, cc = i & 63;
        o4[(size_t)(m0 + r) * (DV / 4) + cc] = e4[(size_t)sidx[r] * (DV / 4) + cc];
    }
}

/* ---------------- Kernel C: finalize loss ---------------- */
__global__ void vq_finalize(float* loss_out, double inv_n) {
    if (threadIdx.x == 0) *loss_out = (float)(2.0 * g_loss_acc * inv_n);
}

extern "C" void kernel_launch(void* const* d_in, const int* in_sizes, int n_in,
                              void* d_out, int out_size) {
    const float* x   = (const float*)d_in[0];
    const float* emb = (const float*)d_in[1];
    float* out = (float*)d_out;
    const int nx = in_sizes[0];          /* 64*32*32*256 = 16777216 */
    const int rows = nx / DV;            /* 65536 */

    cudaFuncSetAttribute(vq_main, cudaFuncAttributeMaxDynamicSharedMemorySize, SMEM_TOTAL);

    vq_prep<<<KEMB, 256>>>(emb);
    vq_main<<<rows / MTILE, 256, SMEM_TOTAL>>>(x, emb, out);
    vq_finalize<<<1, 32>>>(out + (out_size - 1), 1.0 / (double)nx);
}